// round 10
// baseline (speedup 1.0000x reference)
#include <cuda_runtime.h>
#include <cuda_fp16.h>
#include <cstdint>

#define NN 2048
#define HH 256
#define NJ 5
#define RSQ2 0.70710678118654752440f

#define NA ((size_t)NN * NN)
#define NX ((size_t)NN * HH)
#define NW ((size_t)HH * HH)

// fp16 operands stored as ushort
__device__ unsigned short g_Af[NJ * NA];      // 41.9 MB  [j][node][k]
__device__ unsigned short g_Xf[NJ * NX];      //  5.2 MB  [j][hidden][node]
__device__ unsigned short g_Wf[NJ * NW];      //  0.65 MB [j][h_out][h_in]
__device__ unsigned short g_C1[NJ * NX];      //  5.2 MB  [j][node][h]
__device__ float          g_P1[3 * NJ * NX];  // 31.5 MB: GEMM1 split-K3 partials
__device__ float          g_P2[2 * NJ * NX];  // 21 MB:   GEMM2 split-K2 partials

__device__ __forceinline__ uint32_t smem_u32(const void* p) {
    uint32_t a;
    asm("{ .reg .u64 t; cvta.to.shared.u64 t, %1; cvt.u32.u64 %0, t; }"
        : "=r"(a) : "l"(p));
    return a;
}
__device__ __forceinline__ void cp16(uint32_t dst, const void* src) {
    asm volatile("cp.async.cg.shared.global [%0], [%1], 16;" :: "r"(dst), "l"(src));
}
__device__ __forceinline__ void ldsm4(uint32_t& r0, uint32_t& r1, uint32_t& r2,
                                      uint32_t& r3, uint32_t addr) {
    asm volatile("ldmatrix.sync.aligned.m8n8.x4.shared.b16 {%0,%1,%2,%3}, [%4];"
                 : "=r"(r0), "=r"(r1), "=r"(r2), "=r"(r3) : "r"(addr));
}
__device__ __forceinline__ void mma16816(float* d, const uint32_t* a,
                                         uint32_t b0, uint32_t b1) {
    asm volatile(
        "mma.sync.aligned.m16n8k16.row.col.f32.f16.f16.f32 "
        "{%0,%1,%2,%3}, {%4,%5,%6,%7}, {%8,%9}, {%0,%1,%2,%3};"
        : "+f"(d[0]), "+f"(d[1]), "+f"(d[2]), "+f"(d[3])
        : "r"(a[0]), "r"(a[1]), "r"(a[2]), "r"(a[3]), "r"(b0), "r"(b1));
}

__device__ __forceinline__ void cos5(float4 lo, float4 hi, float f[5]) {
    float s04 = lo.x + hi.x, d04 = lo.x - hi.x;
    float s26 = lo.z + hi.z;
    float s15 = lo.y + hi.y, d15 = lo.y - hi.y;
    float s37 = lo.w + hi.w, d37 = lo.w - hi.w;
    float t = RSQ2 * (d15 - d37);
    f[0] = (s04 + s26) + (s15 + s37);
    f[1] = d04 + t;
    f[2] = s04 - s26;
    f[3] = d04 - t;
    f[4] = (s04 + s26) - (s15 + s37);
}
__device__ __forceinline__ unsigned short h16(float f) {
    __half h = __float2half_rn(f);
    return *reinterpret_cast<unsigned short*>(&h);
}

// A: [n1][n2][8] -> Af [j][n1*NN+n2] fp16; 8 elements/thread, 16B stores
__global__ void fwd_A_kernel(const float* __restrict__ in,
                             unsigned short* __restrict__ o, size_t n) {
    size_t i0 = ((size_t)blockIdx.x * blockDim.x + threadIdx.x) * 8;
    if (i0 >= n) return;
    const float4* p = reinterpret_cast<const float4*>(in) + 2 * i0;
    unsigned short h[8][5];
#pragma unroll
    for (int e = 0; e < 8; e++) {
        float f[5]; cos5(p[2 * e], p[2 * e + 1], f);
#pragma unroll
        for (int j = 0; j < 5; j++) h[e][j] = h16(f[j]);
    }
#pragma unroll
    for (int j = 0; j < 5; j++) {
        *reinterpret_cast<uint4*>(o + j * n + i0) =
            make_uint4((uint32_t)h[0][j] | ((uint32_t)h[1][j] << 16),
                       (uint32_t)h[2][j] | ((uint32_t)h[3][j] << 16),
                       (uint32_t)h[4][j] | ((uint32_t)h[5][j] << 16),
                       (uint32_t)h[6][j] | ((uint32_t)h[7][j] << 16));
    }
}

// src [R][C][8] -> out [j][C][R] fp16 (transpose + cos)
__global__ void fwd_T_kernel(const float* __restrict__ in,
                             unsigned short* __restrict__ o,
                             int R, int C) {
    int i = blockIdx.x * blockDim.x + threadIdx.x;
    size_t n = (size_t)R * C;
    if (i >= (int)n) return;
    int c = i / R, r = i - c * R;
    const float4* p = reinterpret_cast<const float4*>(in) + 2 * ((size_t)r * C + c);
    float f[5]; cos5(p[0], p[1], f);
#pragma unroll
    for (int j = 0; j < 5; j++) o[j * n + i] = h16(f[j]);
}

// sum 3 split-K partials of GEMM1 -> fp16 C1
__global__ void reduce3_kernel(const float* __restrict__ P,
                               unsigned short* __restrict__ o) {
    size_t i0 = ((size_t)blockIdx.x * blockDim.x + threadIdx.x) * 4;
    size_t slice = i0 / NX;
    size_t r = i0 - slice * NX;
    const float* base = P + 3 * slice * NX + r;
    float4 s = *reinterpret_cast<const float4*>(base);
#pragma unroll
    for (int q = 1; q < 3; q++) {
        float4 v = *reinterpret_cast<const float4*>(base + q * NX);
        s.x += v.x; s.y += v.y; s.z += v.z; s.w += v.w;
    }
    *reinterpret_cast<uint2*>(o + i0) =
        make_uint2((uint32_t)h16(s.x) | ((uint32_t)h16(s.y) << 16),
                   (uint32_t)h16(s.z) | ((uint32_t)h16(s.w) << 16));
}

// inverse cos transform; folds GEMM2's 2-way split-K reduction
__global__ void inv_kernel(const float* __restrict__ P2,
                           float* __restrict__ out, int n) {
    int i = blockIdx.x * blockDim.x + threadIdx.x;
    if (i >= n) return;
    float g[5];
#pragma unroll
    for (int j = 0; j < 5; j++)
        g[j] = P2[(size_t)(2 * j) * NX + i] + P2[(size_t)(2 * j + 1) * NX + i];
    float d13 = 2.0f * RSQ2 * (g[1] - g[3]);
    float o0 = 0.125f * (g[0] + 2.0f * (g[1] + g[2] + g[3]) + g[4]);
    float o1 = 0.125f * ((g[0] - g[4]) + d13);
    float o2 = 0.125f * ((g[0] + g[4]) - 2.0f * g[2]);
    float o3 = 0.125f * ((g[0] - g[4]) - d13);
    float o4 = 0.125f * (g[0] - 2.0f * (g[1] - g[2] + g[3]) + g[4]);
    reinterpret_cast<float4*>(out)[(size_t)2 * i]     = make_float4(o0, o1, o2, o3);
    reinterpret_cast<float4*>(out)[(size_t)2 * i + 1] = make_float4(o4, o3, o2, o1);
}

// ---------------- fp16 mma.sync GEMM with split-K ---------------------------
// blockIdx.z = slice*splitCnt + part; CTA does chunks [part*nPer, min(kTot,..))
// into its own fp32 slab outP + z*NX.
// Warp-staggered s-order: warp w starts its k-subchunk loop at (wid&3), so at
// any instant warps are in different LDSM/MMA phases -> crossbar and tensor
// pipes overlap instead of phase-locking at the chunk barrier.
#define BM 128
#define BN 128
#define ASTG (BM * 128)
#define BSTG (BN * 128)
#define STGB (ASTG + BSTG)
#define STAGES 3
#define GSMEM (STAGES * STGB)

__device__ __forceinline__ uint32_t swz(int row, int cbyte) {
    return (uint32_t)(row * 128 + (cbyte ^ ((row & 7) << 4)));
}

__global__ __launch_bounds__(256) void gemm_kernel(
    const unsigned short* __restrict__ A, int lda, size_t sA,
    const unsigned short* __restrict__ B, int ldb, size_t sB,
    float* __restrict__ outP, int nPer, int splitCnt, int kTot)
{
    extern __shared__ char smem[];
    const uint32_t sbase = smem_u32(smem);
    const int tid = threadIdx.x;
    const int wid = tid >> 5;
    const int lane = tid & 31;
    const int z = blockIdx.z;
    const int slice = z / splitCnt;
    const int part = z - slice * splitCnt;
    const int ktBegin = part * nPer;
    const int ktEnd = min(ktBegin + nPer, kTot);
    const int m0 = blockIdx.x * BM;
    const int n0 = blockIdx.y * BN;

    A += slice * sA;
    B += slice * sB;
    outP += (size_t)z * NX;

    const int lrow = tid >> 3;          // 0..31
    const int lc16 = (tid & 7) << 4;    // byte col 0..112
    auto load_stage = [&](int s, int ktl) {
        int kk = ktl * 64;
        uint32_t ab = sbase + s * STGB;
        uint32_t bb = ab + ASTG;
#pragma unroll
        for (int t = 0; t < 4; t++) {
            int row = lrow + t * 32;
            cp16(ab + swz(row, lc16), A + (size_t)(m0 + row) * lda + kk + (lc16 >> 1));
        }
#pragma unroll
        for (int t = 0; t < 4; t++) {
            int row = lrow + t * 32;
            cp16(bb + swz(row, lc16), B + (size_t)(n0 + row) * ldb + kk + (lc16 >> 1));
        }
        asm volatile("cp.async.commit_group;" ::: "memory");
    };

    // warp tiling: 2 (M) x 4 (N) warps, warp tile 64x32
    const int wm = (wid >> 2) * 64;
    const int wn = (wid & 3) * 32;
    const int sOff = wid & 3;           // per-warp s-phase stagger

    float d[4][4][4];
#pragma unroll
    for (int i = 0; i < 4; i++)
#pragma unroll
        for (int j = 0; j < 4; j++)
#pragma unroll
            for (int r = 0; r < 4; r++) d[i][j][r] = 0.0f;

    const int aRow = wm + (lane & 7) + ((lane >> 3) & 1) * 8;   // + f*16
    const int aC16 = ((lane >> 4) & 1) * 16;                     // + s*32
    const int bRow = wn + (lane & 7) + ((lane >> 4) & 1) * 8;   // + p*16
    const int bC16 = ((lane >> 3) & 1) * 16;                     // + s*32

    load_stage(0, ktBegin);
    if (ktBegin + 1 < ktEnd) load_stage(1, ktBegin + 1);

    for (int kt = ktBegin; kt < ktEnd; ++kt) {
        if (kt + 1 < ktEnd) asm volatile("cp.async.wait_group 1;" ::: "memory");
        else                asm volatile("cp.async.wait_group 0;" ::: "memory");
        __syncthreads();
        if (kt + 2 < ktEnd) load_stage((kt + 2 - ktBegin) % STAGES, kt + 2);

        uint32_t ab = sbase + ((kt - ktBegin) % STAGES) * STGB;
        uint32_t bb = ab + ASTG;

#pragma unroll
        for (int si = 0; si < 4; si++) {
            int s = (si + sOff) & 3;
            uint32_t a[4][4];
#pragma unroll
            for (int f = 0; f < 4; f++) {
                int row = aRow + f * 16;
                ldsm4(a[f][0], a[f][1], a[f][2], a[f][3],
                      ab + swz(row, s * 32 + aC16));
            }
            uint32_t b[2][4];
#pragma unroll
            for (int p = 0; p < 2; p++) {
                int row = bRow + p * 16;
                ldsm4(b[p][0], b[p][1], b[p][2], b[p][3],
                      bb + swz(row, s * 32 + bC16));
            }
#pragma unroll
            for (int mf = 0; mf < 4; mf++)
#pragma unroll
                for (int nf = 0; nf < 4; nf++) {
                    int p = nf >> 1, h = nf & 1;
                    mma16816(d[mf][nf], a[mf], b[p][h * 2], b[p][h * 2 + 1]);
                }
        }
    }

    const int q = lane >> 2;
    const int cp2 = (lane & 3) * 2;
#pragma unroll
    for (int mf = 0; mf < 4; mf++) {
#pragma unroll
        for (int nf = 0; nf < 4; nf++) {
            int row = m0 + wm + mf * 16 + q;
            int col = n0 + wn + nf * 8 + cp2;
#pragma unroll
            for (int half = 0; half < 2; half++) {
                size_t off = (size_t)(row + half * 8) * HH + col;
                *reinterpret_cast<float2*>(outP + off) =
                    make_float2(d[mf][nf][half * 2], d[mf][nf][half * 2 + 1]);
            }
        }
    }
}

extern "C" void kernel_launch(void* const* d_in, const int* in_sizes, int n_in,
                              void* d_out, int out_size) {
    const float* X = nullptr; const float* A = nullptr; const float* W = nullptr;
    for (int i = 0; i < n_in; i++) {
        if (in_sizes[i] == NN * NN * 8)      A = (const float*)d_in[i];
        else if (in_sizes[i] == NN * HH * 8) X = (const float*)d_in[i];
        else if (in_sizes[i] == HH * HH * 8) W = (const float*)d_in[i];
    }
    float* out = (float*)d_out;

    unsigned short *pAf, *pXf, *pWf, *pC1;
    float *pP1, *pP2;
    cudaGetSymbolAddress((void**)&pAf, g_Af);
    cudaGetSymbolAddress((void**)&pXf, g_Xf);
    cudaGetSymbolAddress((void**)&pWf, g_Wf);
    cudaGetSymbolAddress((void**)&pC1, g_C1);
    cudaGetSymbolAddress((void**)&pP1, g_P1);
    cudaGetSymbolAddress((void**)&pP2, g_P2);

    cudaFuncSetAttribute(gemm_kernel,
                         cudaFuncAttributeMaxDynamicSharedMemorySize, GSMEM);

    fwd_A_kernel<<<(int)(NA / 8 / 256), 256>>>(A, pAf, NA);
    fwd_T_kernel<<<(int)((NX + 255) / 256), 256>>>(X, pXf, NN, HH);
    fwd_T_kernel<<<(int)((NW + 255) / 256), 256>>>(W, pWf, HH, HH);

    // GEMM1: K = 2048 -> 32 chunks, split-K3 (11/11/10); grid 480 CTAs
    dim3 grid1(NN / BM, HH / BN, 3 * NJ);
    gemm_kernel<<<grid1, 256, GSMEM>>>(
        pAf, NN, NA, pXf, NN, NX, pP1, 11, 3, 32);

    // reduce GEMM1 partials -> C1 fp16
    reduce3_kernel<<<(int)(NJ * NX / 4 / 256), 256>>>(pP1, pC1);

    // GEMM2: K = 256 -> 4 chunks, split-K2 (2/2); grid 320 CTAs
    dim3 grid2(NN / BM, HH / BN, 2 * NJ);
    gemm_kernel<<<grid2, 256, GSMEM>>>(
        pC1, HH, NX, pWf, HH, NW, pP2, 2, 2, 4);

    // inverse transform (folds GEMM2 partial reduction)
    inv_kernel<<<(int)((NX + 255) / 256), 256>>>(pP2, out, (int)NX);
}